// round 4
// baseline (speedup 1.0000x reference)
#include <cuda_runtime.h>
#include <math_constants.h>
#include <stdint.h>

// ---------------------------------------------------------------------------
// TopLoss: loss = t01 + t0 + t1 + t2
//   len_k[i] = dgm_k[i,0] - dgm_k[i,1]   (non-finite -> 0)
//   m = max(len_0); t01 = 1-m^2; t0 = sum(len_0^2)-m^2; t1/t2 = sum(len^2)
// Output: [loss, t01, t0, t1, t2] float32.
//
// Single fused kernel: simple grid-stride streaming loop (3 independent
// float4 __ldcs loads per iter), block partials -> last-block finalize
// (integer atomic arrival; fixed-order fp32 tree reduce => deterministic).
// ---------------------------------------------------------------------------

#define NB 1184            // 148 SMs * 8 blocks
#define NT 256

__device__ float g_part[NB * 4];   // {s0, s1, s2, max0} per block
__device__ int   g_sem = 0;        // arrival counter (reset by last block)

__device__ __forceinline__ float sanitized_len(float a, float b) {
    float l = a - b;
    return isfinite(l) ? l : 0.0f;
}

__device__ __forceinline__ float warp_sum(float v) {
#pragma unroll
    for (int o = 16; o > 0; o >>= 1) v += __shfl_down_sync(0xFFFFFFFFu, v, o);
    return v;
}
__device__ __forceinline__ float warp_max(float v) {
#pragma unroll
    for (int o = 16; o > 0; o >>= 1) v = fmaxf(v, __shfl_down_sync(0xFFFFFFFFu, v, o));
    return v;
}

__global__ __launch_bounds__(NT, 6) void toploss_kernel(
    const float4* __restrict__ d0,
    const float4* __restrict__ d1,
    const float4* __restrict__ d2,
    long n4,            // float4 elements per array
    long n_floats,      // floats per array (scalar tail)
    float* __restrict__ out)
{
    float s0 = 0.0f, s1 = 0.0f, s2 = 0.0f;
    float m0 = -CUDART_INF_F;

    const long stride = (long)gridDim.x * blockDim.x;
    for (long i = (long)blockIdx.x * blockDim.x + threadIdx.x; i < n4; i += stride) {
        // three independent 16B streaming loads (evict-first: touched once)
        float4 a = __ldcs(&d0[i]);
        float4 b = __ldcs(&d1[i]);
        float4 c = __ldcs(&d2[i]);

        float la = sanitized_len(a.x, a.y);
        float lb = sanitized_len(a.z, a.w);
        s0 += la * la + lb * lb;
        m0 = fmaxf(m0, fmaxf(la, lb));

        la = sanitized_len(b.x, b.y);
        lb = sanitized_len(b.z, b.w);
        s1 += la * la + lb * lb;

        la = sanitized_len(c.x, c.y);
        lb = sanitized_len(c.z, c.w);
        s2 += la * la + lb * lb;
    }

    // scalar tail (pairs beyond n4*4 floats) — one thread; n=16M means none
    if (blockIdx.x == 0 && threadIdx.x == 0) {
        const float* f0 = (const float*)d0;
        const float* f1 = (const float*)d1;
        const float* f2 = (const float*)d2;
        for (long j = n4 * 4; j + 1 < n_floats; j += 2) {
            float l0 = sanitized_len(f0[j], f0[j + 1]);
            s0 += l0 * l0;
            m0 = fmaxf(m0, l0);
            float l1 = sanitized_len(f1[j], f1[j + 1]);
            s1 += l1 * l1;
            float l2 = sanitized_len(f2[j], f2[j + 1]);
            s2 += l2 * l2;
        }
    }

    // ---- block reduction ----
    __shared__ float sh[4][NT / 32];
    s0 = warp_sum(s0);
    s1 = warp_sum(s1);
    s2 = warp_sum(s2);
    m0 = warp_max(m0);
    int lane = threadIdx.x & 31;
    int wid  = threadIdx.x >> 5;
    if (lane == 0) {
        sh[0][wid] = s0;
        sh[1][wid] = s1;
        sh[2][wid] = s2;
        sh[3][wid] = m0;
    }
    __syncthreads();
    __shared__ bool is_last;
    if (wid == 0) {
        const int nw = NT / 32;
        float v0 = (lane < nw) ? sh[0][lane] : 0.0f;
        float v1 = (lane < nw) ? sh[1][lane] : 0.0f;
        float v2 = (lane < nw) ? sh[2][lane] : 0.0f;
        float vm = (lane < nw) ? sh[3][lane] : -CUDART_INF_F;
        v0 = warp_sum(v0);
        v1 = warp_sum(v1);
        v2 = warp_sum(v2);
        vm = warp_max(vm);
        if (lane == 0) {
            g_part[blockIdx.x * 4 + 0] = v0;
            g_part[blockIdx.x * 4 + 1] = v1;
            g_part[blockIdx.x * 4 + 2] = v2;
            g_part[blockIdx.x * 4 + 3] = vm;
            __threadfence();                       // publish partials
            int prev = atomicAdd(&g_sem, 1);       // integer -> deterministic
            is_last = (prev == gridDim.x - 1);
        }
    }
    __syncthreads();

    // ---- last block finalizes (fixed-order read => bit-stable output) ----
    if (is_last) {
        __threadfence();   // acquire partials published by other blocks
        float a0 = 0.0f, a1 = 0.0f, a2 = 0.0f;
        float am = -CUDART_INF_F;
        for (int k = threadIdx.x; k < NB; k += NT) {
            a0 += g_part[k * 4 + 0];
            a1 += g_part[k * 4 + 1];
            a2 += g_part[k * 4 + 2];
            am = fmaxf(am, g_part[k * 4 + 3]);
        }
        a0 = warp_sum(a0);
        a1 = warp_sum(a1);
        a2 = warp_sum(a2);
        am = warp_max(am);
        __shared__ float fs[4][NT / 32];
        if (lane == 0) {
            fs[0][wid] = a0;
            fs[1][wid] = a1;
            fs[2][wid] = a2;
            fs[3][wid] = am;
        }
        __syncthreads();
        if (wid == 0) {
            const int nw = NT / 32;
            float v0 = (lane < nw) ? fs[0][lane] : 0.0f;
            float v1 = (lane < nw) ? fs[1][lane] : 0.0f;
            float v2 = (lane < nw) ? fs[2][lane] : 0.0f;
            float vm = (lane < nw) ? fs[3][lane] : -CUDART_INF_F;
            v0 = warp_sum(v0);
            v1 = warp_sum(v1);
            v2 = warp_sum(v2);
            vm = warp_max(vm);
            if (lane == 0) {
                float m2  = vm * vm;
                float t01 = 1.0f - m2;
                float t0  = v0 - m2;
                float loss = t01 + t0 + v1 + v2;
                out[0] = loss;
                out[1] = t01;
                out[2] = t0;
                out[3] = v1;
                out[4] = v2;
                g_sem = 0;   // reset for next graph replay
            }
        }
    }
}

extern "C" void kernel_launch(void* const* d_in, const int* in_sizes, int n_in,
                              void* d_out, int out_size) {
    const float* d0 = (const float*)d_in[0];
    const float* d1 = (const float*)d_in[1];
    const float* d2 = (const float*)d_in[2];
    float* out = (float*)d_out;

    long n_floats = (long)in_sizes[0];  // 2 * N_BARS = 16M
    long n4 = n_floats / 4;

    toploss_kernel<<<NB, NT>>>((const float4*)d0, (const float4*)d1,
                               (const float4*)d2, n4, n_floats, out);
}

// round 6
// speedup vs baseline: 1.0616x; 1.0616x over previous
#include <cuda_runtime.h>
#include <math_constants.h>
#include <stdint.h>

// ---------------------------------------------------------------------------
// TopLoss: loss = t01 + t0 + t1 + t2
//   len_k[i] = dgm_k[i,0] - dgm_k[i,1]   (non-finite -> 0)
//   m = max(len_0); t01 = 1-m^2; t0 = sum(len_0^2)-m^2; t1/t2 = sum(len^2)
// Output: [loss, t01, t0, t1, t2] float32.
//
// Single fused kernel. Streaming geometry copied from the measured-best R2
// config: NB=1024 x NT=256 -> every thread does EXACTLY 16 uniform
// grid-stride iterations over each of the 3 arrays (4M float4 / 262144 thr).
// Block partials -> last-block finalize (integer atomic arrival; fixed-order
// fp32 tree reduce => deterministic, graph-replay bit-stable).
// ---------------------------------------------------------------------------

#define NB 1024
#define NT 256

__device__ float g_part[NB * 4];   // {s0, s1, s2, max0} per block
__device__ int   g_sem = 0;        // arrival counter (reset by last block)

__device__ __forceinline__ float sanitized_len(float a, float b) {
    float l = a - b;
    return isfinite(l) ? l : 0.0f;
}

__device__ __forceinline__ float warp_sum(float v) {
#pragma unroll
    for (int o = 16; o > 0; o >>= 1) v += __shfl_down_sync(0xFFFFFFFFu, v, o);
    return v;
}
__device__ __forceinline__ float warp_max(float v) {
#pragma unroll
    for (int o = 16; o > 0; o >>= 1) v = fmaxf(v, __shfl_down_sync(0xFFFFFFFFu, v, o));
    return v;
}

__global__ __launch_bounds__(NT) void toploss_kernel(
    const float4* __restrict__ d0,
    const float4* __restrict__ d1,
    const float4* __restrict__ d2,
    long n4,            // float4 elements per array
    long n_floats,      // floats per array (scalar tail)
    float* __restrict__ out)
{
    float s0 = 0.0f, s1 = 0.0f, s2 = 0.0f;
    float m0 = -CUDART_INF_F;

    const long stride = (long)gridDim.x * blockDim.x;
    for (long i = (long)blockIdx.x * blockDim.x + threadIdx.x; i < n4; i += stride) {
        // three independent 16B load streams -> MLP >= 3 before any use
        float4 a = d0[i];
        float4 b = d1[i];
        float4 c = d2[i];

        float la = sanitized_len(a.x, a.y);
        float lb = sanitized_len(a.z, a.w);
        s0 += la * la + lb * lb;
        m0 = fmaxf(m0, fmaxf(la, lb));

        la = sanitized_len(b.x, b.y);
        lb = sanitized_len(b.z, b.w);
        s1 += la * la + lb * lb;

        la = sanitized_len(c.x, c.y);
        lb = sanitized_len(c.z, c.w);
        s2 += la * la + lb * lb;
    }

    // scalar tail (pairs beyond n4*4 floats) — one thread; n=16M means none
    if (blockIdx.x == 0 && threadIdx.x == 0) {
        const float* f0 = (const float*)d0;
        const float* f1 = (const float*)d1;
        const float* f2 = (const float*)d2;
        for (long j = n4 * 4; j + 1 < n_floats; j += 2) {
            float l0 = sanitized_len(f0[j], f0[j + 1]);
            s0 += l0 * l0;
            m0 = fmaxf(m0, l0);
            float l1 = sanitized_len(f1[j], f1[j + 1]);
            s1 += l1 * l1;
            float l2 = sanitized_len(f2[j], f2[j + 1]);
            s2 += l2 * l2;
        }
    }

    // ---- block reduction ----
    __shared__ float sh[4][NT / 32];
    s0 = warp_sum(s0);
    s1 = warp_sum(s1);
    s2 = warp_sum(s2);
    m0 = warp_max(m0);
    int lane = threadIdx.x & 31;
    int wid  = threadIdx.x >> 5;
    if (lane == 0) {
        sh[0][wid] = s0;
        sh[1][wid] = s1;
        sh[2][wid] = s2;
        sh[3][wid] = m0;
    }
    __syncthreads();
    __shared__ bool is_last;
    if (wid == 0) {
        const int nw = NT / 32;
        float v0 = (lane < nw) ? sh[0][lane] : 0.0f;
        float v1 = (lane < nw) ? sh[1][lane] : 0.0f;
        float v2 = (lane < nw) ? sh[2][lane] : 0.0f;
        float vm = (lane < nw) ? sh[3][lane] : -CUDART_INF_F;
        v0 = warp_sum(v0);
        v1 = warp_sum(v1);
        v2 = warp_sum(v2);
        vm = warp_max(vm);
        if (lane == 0) {
            g_part[blockIdx.x * 4 + 0] = v0;
            g_part[blockIdx.x * 4 + 1] = v1;
            g_part[blockIdx.x * 4 + 2] = v2;
            g_part[blockIdx.x * 4 + 3] = vm;
            __threadfence();                       // publish partials
            int prev = atomicAdd(&g_sem, 1);       // integer -> deterministic
            is_last = (prev == gridDim.x - 1);
        }
    }
    __syncthreads();

    // ---- last block finalizes (fixed-order read => bit-stable output) ----
    if (is_last) {
        __threadfence();   // acquire partials published by other blocks
        float a0 = 0.0f, a1 = 0.0f, a2 = 0.0f;
        float am = -CUDART_INF_F;
        for (int k = threadIdx.x; k < NB; k += NT) {
            a0 += g_part[k * 4 + 0];
            a1 += g_part[k * 4 + 1];
            a2 += g_part[k * 4 + 2];
            am = fmaxf(am, g_part[k * 4 + 3]);
        }
        a0 = warp_sum(a0);
        a1 = warp_sum(a1);
        a2 = warp_sum(a2);
        am = warp_max(am);
        __shared__ float fs[4][NT / 32];
        if (lane == 0) {
            fs[0][wid] = a0;
            fs[1][wid] = a1;
            fs[2][wid] = a2;
            fs[3][wid] = am;
        }
        __syncthreads();
        if (wid == 0) {
            const int nw = NT / 32;
            float v0 = (lane < nw) ? fs[0][lane] : 0.0f;
            float v1 = (lane < nw) ? fs[1][lane] : 0.0f;
            float v2 = (lane < nw) ? fs[2][lane] : 0.0f;
            float vm = (lane < nw) ? fs[3][lane] : -CUDART_INF_F;
            v0 = warp_sum(v0);
            v1 = warp_sum(v1);
            v2 = warp_sum(v2);
            vm = warp_max(vm);
            if (lane == 0) {
                float m2  = vm * vm;
                float t01 = 1.0f - m2;
                float t0  = v0 - m2;
                float loss = t01 + t0 + v1 + v2;
                out[0] = loss;
                out[1] = t01;
                out[2] = t0;
                out[3] = v1;
                out[4] = v2;
                g_sem = 0;   // reset for next graph replay
            }
        }
    }
}

extern "C" void kernel_launch(void* const* d_in, const int* in_sizes, int n_in,
                              void* d_out, int out_size) {
    const float* d0 = (const float*)d_in[0];
    const float* d1 = (const float*)d_in[1];
    const float* d2 = (const float*)d_in[2];
    float* out = (float*)d_out;

    long n_floats = (long)in_sizes[0];  // 2 * N_BARS = 16M
    long n4 = n_floats / 4;

    toploss_kernel<<<NB, NT>>>((const float4*)d0, (const float4*)d1,
                               (const float4*)d2, n4, n_floats, out);
}